// round 13
// baseline (speedup 1.0000x reference)
#include <cuda_runtime.h>
#include <math.h>

#define B_ 16
#define N_ 2048
#define D_ 256
#define K_ 8
#define H_ 4
#define HID_ 1024
#define LN_EPS 1e-5f
#define SCALEF 0.0625f   // 256^-0.5
#define TT_ 32           // tokens per attn tile
#define NT_ 64           // token tiles (N_/TT_)
#define EST 260          // emb_sh row stride (floats)
#define WST 260          // w_sh row stride
#define DST 36           // dots_sh row stride (conflict-free scatter)
#define NB2_ 256         // mega-kernel blocks

// packed f32x2 FMA helpers
#define FMA2(acc, a, b) \
    asm("fma.rn.f32x2 %0, %1, %2, %0;" : "+l"(acc) : "l"(a), "l"(b))
#define DUP2(dst, f) \
    asm("mov.b64 %0, {%1, %1};" : "=l"(dst) : "f"(f))
#define UNPK2(lo, hi, v) \
    asm("mov.b64 {%0, %1}, %2;" : "=f"(lo), "=f"(hi) : "l"(v))

// ------------------- static device scratch (no allocations) -------------------
static __device__ float g_emb  [B_*N_*D_];
static __device__ float g_slots[B_*K_*D_];
static __device__ float g_w    [B_*K_*H_*D_];     // folded weights [b][kh][e]
static __device__ float g_aggp [B_*NT_*K_*D_];
static __device__ float g_rsp  [B_*NT_*K_];
static __device__ float g_updp [2*B_*K_*D_];
static __device__ float g_gi   [B_*K_*3*D_];
static __device__ float g_gh   [B_*K_*3*D_];
static __device__ float g_pre  [B_*K_*D_];
static __device__ float g_m2p  [8*B_*K_*D_];      // mlp2 split-K partials

// device barrier state
static __device__ unsigned          g_cnt = 0;
static __device__ volatile unsigned g_gen = 0;

__device__ __forceinline__ void gsync() {
    __syncthreads();
    if (threadIdx.x == 0) {
        __threadfence();
        unsigned gen = g_gen;
        if (atomicAdd(&g_cnt, 1) == NB2_ - 1) {
            g_cnt = 0;
            __threadfence();
            g_gen = gen + 1;
        } else {
            while (g_gen == gen) { }
        }
        __threadfence();
    }
    __syncthreads();
}

// ------------------- slots = mu + exp(logsigma)*noise -------------------
__global__ void k_init_slots(const float* __restrict__ mu, const float* __restrict__ ls,
                             const float* __restrict__ nz) {
    int i = blockIdx.x * 256 + threadIdx.x;
    int kd = i & (K_*D_ - 1);
    g_slots[i] = mu[kd] + __expf(ls[kd]) * nz[i];
}

// ------------------- embeddings LayerNorm (one warp per row) -------------------
__global__ __launch_bounds__(256) void k_lnemb(const float* __restrict__ xin,
                                               const float* __restrict__ g,
                                               const float* __restrict__ b) {
    int wid = threadIdx.x >> 5, lane = threadIdx.x & 31;
    size_t row = (size_t)blockIdx.x * 8 + wid;
    const float* xr = xin + row * D_;
    float4 v0 = ((const float4*)xr)[lane];
    float4 v1 = ((const float4*)xr)[32 + lane];
    float s = v0.x+v0.y+v0.z+v0.w + v1.x+v1.y+v1.z+v1.w;
    float q = v0.x*v0.x+v0.y*v0.y+v0.z*v0.z+v0.w*v0.w
            + v1.x*v1.x+v1.y*v1.y+v1.z*v1.z+v1.w*v1.w;
    #pragma unroll
    for (int o = 16; o; o >>= 1) {
        s += __shfl_xor_sync(0xffffffffu, s, o);
        q += __shfl_xor_sync(0xffffffffu, q, o);
    }
    float m  = s * (1.0f / D_);
    float rs = rsqrtf(q * (1.0f / D_) - m * m + LN_EPS);
    float4 g0 = ((const float4*)g)[lane],      b0 = ((const float4*)b)[lane];
    float4 g1 = ((const float4*)g)[32 + lane], b1 = ((const float4*)b)[32 + lane];
    float4 o0, o1;
    o0.x = (v0.x-m)*rs*g0.x + b0.x;  o0.y = (v0.y-m)*rs*g0.y + b0.y;
    o0.z = (v0.z-m)*rs*g0.z + b0.z;  o0.w = (v0.w-m)*rs*g0.w + b0.w;
    o1.x = (v1.x-m)*rs*g1.x + b1.x;  o1.y = (v1.y-m)*rs*g1.y + b1.y;
    o1.z = (v1.z-m)*rs*g1.z + b1.z;  o1.w = (v1.w-m)*rs*g1.w + b1.w;
    ((float4*)(g_emb + row * D_))[lane]      = o0;
    ((float4*)(g_emb + row * D_))[32 + lane] = o1;
}

// ---- shared body: slot value x for row (b,k) -> LN(ln_sl) -> q -> fold w (full row) ----
__device__ __forceinline__ void wfold_row(float x, int b, int k, int t,
                                          const float* __restrict__ tq,
                                          const float* __restrict__ tk,
                                          const float* __restrict__ lg,
                                          const float* __restrict__ lb,
                                          float* red, float* q_sh) {
    float s = x, q = x * x;
    #pragma unroll
    for (int o = 16; o; o >>= 1) {
        s += __shfl_xor_sync(0xffffffffu, s, o);
        q += __shfl_xor_sync(0xffffffffu, q, o);
    }
    if ((t & 31) == 0) { red[t >> 5] = s; red[8 + (t >> 5)] = q; }
    __syncthreads();
    float S = 0.0f, Q = 0.0f;
    #pragma unroll
    for (int i = 0; i < 8; i++) { S += red[i]; Q += red[8 + i]; }
    float m  = S * (1.0f / D_);
    float rs = rsqrtf(Q * (1.0f / D_) - m * m + LN_EPS);
    float sv = (x - m) * rs * lg[t] + lb[t];
    q_sh[t] = sv * tq[(size_t)k * 65536 + t * 257];
    __syncthreads();
    const float* tr = tk + (size_t)k * 65536 + (size_t)t * D_;
    #pragma unroll
    for (int h = 0; h < H_; h++) {
        const float4* r4 = (const float4*)(tr + h * 64);
        const float4* q4 = (const float4*)(q_sh + h * 64);
        float a = 0.0f;
        #pragma unroll
        for (int j = 0; j < 16; j++) {
            float4 rv = r4[j], qv = q4[j];
            a += rv.x*qv.x + rv.y*qv.y + rv.z*qv.z + rv.w*qv.w;
        }
        g_w[((size_t)(b * 32 + k * 4 + h)) * D_ + t] = SCALEF * a;
    }
}

// ------------------- standalone first-iteration w-fold -------------------
__global__ __launch_bounds__(256) void k_w0(const float* __restrict__ tq,
                                            const float* __restrict__ tk,
                                            const float* __restrict__ lg,
                                            const float* __restrict__ lb) {
    __shared__ float red[16];
    __shared__ float q_sh[D_];
    int bk = blockIdx.x, b = bk >> 3, k = bk & 7, t = threadIdx.x;
    float x = g_slots[(size_t)bk * D_ + t];
    wfold_row(x, b, k, t, tq, tk, lg, lb, red, q_sh);
}

// ------------------- fused attention v7: attn tiles + piggybacked gh GEMM -------------------
// grid (64, 17): y<16 -> attn tile (batch=y, tile=x); y==16 -> gh GEMM tile (64 blocks).
// gh = slots_prev @ whh^T + bhh runs in attn's SM shadow (depends only on g_slots).
__global__ __launch_bounds__(256, 3) void k_attn(float* __restrict__ vis, int wvis,
                                                 const float* __restrict__ whh,
                                                 const float* __restrict__ bhh) {
    extern __shared__ __align__(16) float sm[];
    int tid = threadIdx.x, lane = tid & 31, wid = tid >> 5;

    // ================= gh GEMM branch (blockIdx.y == 16) =================
    if (blockIdx.y == 16) {
        int t2 = blockIdx.x;                 // 0..63
        int m0 = (t2 >> 4) * 32;             // 4 m-tiles of 32
        int n0 = (t2 & 15) * 48;             // 16 n-tiles of 48
        float* As = sm;                      // [32][33]
        float* Bs = sm + 1056;               // [48][33]
        int tx = tid & 15, ty = tid >> 4;    // 16 x 16 threads; thread = 2m x 3n
        float c00=0,c01=0,c02=0,c10=0,c11=0,c12=0;
        for (int k0 = 0; k0 < D_; k0 += 32) {
            #pragma unroll
            for (int r = 0; r < 4; r++) {
                int i = tid + r * 256;
                As[(i >> 5) * 33 + (i & 31)] = g_slots[(size_t)(m0 + (i >> 5)) * D_ + k0 + (i & 31)];
            }
            #pragma unroll
            for (int r = 0; r < 6; r++) {
                int i = tid + r * 256;
                Bs[(i >> 5) * 33 + (i & 31)] = whh[(size_t)(n0 + (i >> 5)) * D_ + k0 + (i & 31)];
            }
            __syncthreads();
            #pragma unroll
            for (int k = 0; k < 32; k++) {
                float a0 = As[(ty*2)*33 + k], a1 = As[(ty*2+1)*33 + k];
                float b0 = Bs[(tx*3)*33 + k], b1 = Bs[(tx*3+1)*33 + k], b2v = Bs[(tx*3+2)*33 + k];
                c00 += a0*b0; c01 += a0*b1; c02 += a0*b2v;
                c10 += a1*b0; c11 += a1*b1; c12 += a1*b2v;
            }
            __syncthreads();
        }
        int m = m0 + ty*2, n = n0 + tx*3;
        g_gh[(size_t)m * 768 + n]       = c00 + bhh[n];
        g_gh[(size_t)m * 768 + n+1]     = c01 + bhh[n+1];
        g_gh[(size_t)m * 768 + n+2]     = c02 + bhh[n+2];
        g_gh[(size_t)(m+1) * 768 + n]   = c10 + bhh[n];
        g_gh[(size_t)(m+1) * 768 + n+1] = c11 + bhh[n+1];
        g_gh[(size_t)(m+1) * 768 + n+2] = c12 + bhh[n+2];
        return;
    }

    // ================= attention branch (unchanged from R12) =================
    float* w_sh    = sm;                    // [kh][e]   32*WST (reused as reduction buffer)
    float* emb_sh  = w_sh + 32 * WST;       // [t][e]    32*EST
    float* dots_sh = emb_sh + TT_ * EST;    // [eh][t][kh] 64*DST
    float* att_sh  = dots_sh + 64 * DST;    // [t][k]    32*9

    int b = blockIdx.y;
    int tile = blockIdx.x;
    int nb = tile * TT_;

    const float4* wsrc = (const float4*)(g_w + (size_t)b * 8192);
    #pragma unroll
    for (int r = 0; r < 8; r++) {
        int j = tid + r * 256;
        *(float4*)(w_sh + (j >> 6) * WST + (j & 63) * 4) = wsrc[j];
    }
    const float4* esrc = (const float4*)(g_emb + ((size_t)(b * N_ + nb)) * D_);
    #pragma unroll
    for (int r = 0; r < 8; r++) {
        int j = tid + r * 256;
        *(float4*)(emb_sh + (j >> 6) * EST + (j & 63) * 4) = esrc[j];
    }
    __syncthreads();

    {
        int unit = wid >> 1, eh = wid & 1;
        int tbase  = (unit >> 1) * 16;
        int khbase = (unit & 1) * 16;
        int lt = lane >> 2, lk = lane & 3;
        int t0  = tbase + lt;
        int kh0 = khbase + lk;
        int e0 = eh * 128;
        const float* eb0 = emb_sh + t0 * EST + e0;
        const float* wb0 = w_sh + kh0 * WST + e0;
        unsigned long long acc2[2][4];
        #pragma unroll
        for (int i = 0; i < 2; i++)
            #pragma unroll
            for (int j = 0; j < 4; j++) acc2[i][j] = 0ull;

        #pragma unroll 4
        for (int e = 0; e < 128; e += 4) {
            ulonglong2 ev0 = *(const ulonglong2*)(eb0 + e);
            ulonglong2 ev1 = *(const ulonglong2*)(eb0 + 8 * EST + e);
            #pragma unroll
            for (int j = 0; j < 4; j++) {
                ulonglong2 wv = *(const ulonglong2*)(wb0 + (4 * j) * WST + e);
                FMA2(acc2[0][j], ev0.x, wv.x);
                FMA2(acc2[0][j], ev0.y, wv.y);
                FMA2(acc2[1][j], ev1.x, wv.x);
                FMA2(acc2[1][j], ev1.y, wv.y);
            }
        }
        #pragma unroll
        for (int i = 0; i < 2; i++)
            #pragma unroll
            for (int j = 0; j < 4; j++) {
                float lo, hi; UNPK2(lo, hi, acc2[i][j]);
                dots_sh[(eh * 32 + t0 + 8 * i) * DST + kh0 + 4 * j] = lo + hi;
            }
    }
    __syncthreads();

    if (tid < 128) {
        int t = tid >> 2, h = tid & 3;
        float d[8], mx = -1e30f;
        #pragma unroll
        for (int k = 0; k < 8; k++) {
            d[k] = dots_sh[t * DST + k*4 + h] + dots_sh[(32 + t) * DST + k*4 + h];
            mx = fmaxf(mx, d[k]);
        }
        float smx = 0.0f;
        #pragma unroll
        for (int k = 0; k < 8; k++) { d[k] = __expf(d[k] - mx); smx += d[k]; }
        float inv = 1.0f / smx;
        #pragma unroll
        for (int k = 0; k < 8; k++) {
            float v = d[k] * inv;
            v += __shfl_xor_sync(0xffffffffu, v, 1);
            v += __shfl_xor_sync(0xffffffffu, v, 2);
            if (h == 0) att_sh[t * 9 + k] = v * 0.25f;
        }
    }
    __syncthreads();

    {
        float rs = att_sh[lane * 9 + wid];
        #pragma unroll
        for (int o = 16; o; o >>= 1) rs += __shfl_xor_sync(0xffffffffu, rs, o);
        if (lane == 0) g_rsp[((size_t)b * NT_ + tile) * K_ + wid] = rs;
        if (wvis)
            vis[((size_t)b * K_ + wid) * N_ + nb + lane] = att_sh[lane * 9 + wid];
    }

    {
        int ts = tid >> 6, eg = tid & 63;
        unsigned long long acc[8][2];
        #pragma unroll
        for (int k = 0; k < 8; k++) { acc[k][0] = 0ull; acc[k][1] = 0ull; }
        const float* ebase = emb_sh + eg * 4;
        #pragma unroll
        for (int tt = 0; tt < 8; tt++) {
            int t = ts * 8 + tt;
            ulonglong2 ev = *(const ulonglong2*)(ebase + t * EST);
            #pragma unroll
            for (int k = 0; k < 8; k++) {
                float a = att_sh[t * 9 + k];
                unsigned long long aa; DUP2(aa, a);
                FMA2(acc[k][0], ev.x, aa);
                FMA2(acc[k][1], ev.y, aa);
            }
        }
        float* red = w_sh;
        #pragma unroll
        for (int k = 0; k < 8; k++) {
            float f0, f1, f2, f3;
            UNPK2(f0, f1, acc[k][0]);
            UNPK2(f2, f3, acc[k][1]);
            *(float4*)(red + (ts * 8 + k) * 256 + eg * 4) = make_float4(f0, f1, f2, f3);
        }
    }
    __syncthreads();
    {
        const float* red = w_sh;
        #pragma unroll
        for (int r = 0; r < 8; r++) {
            int idx = tid + r * 256;
            int k = idx >> 8, e = idx & 255;
            float s = red[k * 256 + e] + red[(8 + k) * 256 + e]
                    + red[(16 + k) * 256 + e] + red[(24 + k) * 256 + e];
            g_aggp[(((size_t)(b * NT_ + tile)) * K_ + k) * D_ + e] = s;
        }
    }
}

// ------------------- mega-kernel v3 (256 blocks, 4 gsyncs; gi-only P1; retiled mlp1) ----
__global__ __launch_bounds__(256, 2) void k_mega(
    const float* __restrict__ tq, const float* __restrict__ tk, const float* __restrict__ tv,
    const float* __restrict__ wih, const float* __restrict__ bih,
    const float* __restrict__ w1, const float* __restrict__ b1g,
    const float* __restrict__ w2, const float* __restrict__ b2,
    const float* __restrict__ ln_sl_g, const float* __restrict__ ln_sl_b,
    const float* __restrict__ ln_ff_g, const float* __restrict__ ln_ff_b,
    int last, float* __restrict__ out)
{
    extern __shared__ __align__(16) float pool[];
    int bid = blockIdx.x, tid = threadIdx.x;

    // ---- P0: upd partials. block = (row, e-half). ----
    {
        int row = bid >> 1, half = bid & 1, b = row >> 3, k = row & 7;
        int e0 = half * 128;
        float acc = 0.0f;
        int e = e0 + (tid & 127);
        int tb = (tid < 128) ? 0 : 32;
        const float* base = g_aggp + ((size_t)(b * NT_) * K_ + k) * D_ + e;
        #pragma unroll 8
        for (int tile = 0; tile < 32; tile++)
            acc += base[(size_t)(tb + tile) * (K_ * D_)];
        pool[tid] = acc;
        if (tid == 0) {
            float r = 0.0f;
            #pragma unroll
            for (int tile = 0; tile < NT_; tile++)
                r += g_rsp[((size_t)b * NT_ + tile) * K_ + k];
            pool[2048] = 1.0f / r;
        }
        __syncthreads();
        const float* tvk = tv + (size_t)k * 65536 + (size_t)e0 * D_ + tid;
        float mv = 0.0f;
        #pragma unroll 8
        for (int e2 = 0; e2 < 128; e2++)
            mv += (pool[e2] + pool[128 + e2]) * __ldg(tvk + (size_t)e2 * D_);
        g_updp[(size_t)half * 32768 + (size_t)row * D_ + tid] = mv * pool[2048];
    }
    gsync();

    // ---- P1: gi = upd @ wih^T + bih, 32x32 tiles (96 blocks; gh done in k_attn) ----
    if (bid < 96) {
        int m0 = (bid / 24) * 32, n0 = (bid % 24) * 32;
        float* As = pool; float* Bs = pool + 32 * 33;
        int tx = tid & 15, ty = tid >> 4;
        float c00 = 0, c01 = 0, c10 = 0, c11 = 0;
        for (int k0 = 0; k0 < D_; k0 += 32) {
            #pragma unroll
            for (int r = 0; r < 4; r++) {
                int i = tid + r * 256;
                int m = m0 + (i >> 5), d = k0 + (i & 31);
                As[(i >> 5) * 33 + (i & 31)] =
                    g_updp[(size_t)m * D_ + d] + g_updp[32768 + (size_t)m * D_ + d];
                Bs[(i >> 5) * 33 + (i & 31)] = wih[(size_t)(n0 + (i >> 5)) * D_ + d];
            }
            __syncthreads();
            #pragma unroll
            for (int k = 0; k < 32; k++) {
                float a0 = As[(ty*2)*33 + k], a1 = As[(ty*2+1)*33 + k];
                float b0 = Bs[(tx*2)*33 + k], b1 = Bs[(tx*2+1)*33 + k];
                c00 += a0*b0; c01 += a0*b1; c10 += a1*b0; c11 += a1*b1;
            }
            __syncthreads();
        }
        int m = m0 + ty*2, n = n0 + tx*2;
        g_gi[(size_t)m * 768 + n]       = c00 + bih[n];
        g_gi[(size_t)m * 768 + n+1]     = c01 + bih[n+1];
        g_gi[(size_t)(m+1) * 768 + n]   = c10 + bih[n];
        g_gi[(size_t)(m+1) * 768 + n+1] = c11 + bih[n+1];
    }
    gsync();

    // ---- P2: GRU gates + pre-MLP LayerNorm(ff) (128 blocks) ----
    if (bid < 128) {
        float* red = pool;
        int row = bid, t = tid;
        const float* gi = g_gi + (size_t)row * 768;
        const float* gh = g_gh + (size_t)row * 768;
        float ir = gi[t], iz = gi[256 + t], in_ = gi[512 + t];
        float hr = gh[t], hz = gh[256 + t], hn  = gh[512 + t];
        float r = 1.0f / (1.0f + __expf(-(ir + hr)));
        float z = 1.0f / (1.0f + __expf(-(iz + hz)));
        float n = tanhf(in_ + r * hn);
        float h = g_slots[(size_t)row * D_ + t];
        float s = (1.0f - z) * n + z * h;
        g_slots[(size_t)row * D_ + t] = s;
        float a = s, q = s * s;
        #pragma unroll
        for (int o = 16; o; o >>= 1) {
            a += __shfl_xor_sync(0xffffffffu, a, o);
            q += __shfl_xor_sync(0xffffffffu, q, o);
        }
        if ((t & 31) == 0) { red[t >> 5] = a; red[8 + (t >> 5)] = q; }
        __syncthreads();
        float S = 0.0f, Q = 0.0f;
        #pragma unroll
        for (int i = 0; i < 8; i++) { S += red[i]; Q += red[8 + i]; }
        float m  = S * (1.0f / D_);
        float rs = rsqrtf(Q * (1.0f / D_) - m * m + LN_EPS);
        g_pre[(size_t)row * D_ + t] = (s - m) * rs * ln_ff_g[t] + ln_ff_b[t];
    }
    gsync();

    // ---- P34 fused: mlp1 tile (4m x 128n, hid in smem) -> mlp2 split-K partial ----
    {
        int mt = bid >> 3, hc = bid & 7;
        int m0 = mt * 4;
        // --- mlp1: thread = 4m x 2n (n = tx, tx+64); 6 LDS per 8 FMA ---
        float* As = pool;            // [4][33]
        float* Bs = pool + 132;      // [128][33]
        int tx = tid & 63;           // n-pair selector; all threads with same tx duplicate m-work
        float c[4][2] = {{0,0},{0,0},{0,0},{0,0}};
        for (int k0 = 0; k0 < D_; k0 += 32) {
            if (tid < 128)
                As[(tid >> 5) * 33 + (tid & 31)] =
                    g_pre[(size_t)(m0 + (tid >> 5)) * D_ + k0 + (tid & 31)];
            #pragma unroll
            for (int r = 0; r < 16; r++) {
                int i = tid + r * 256;
                Bs[(i >> 5) * 33 + (i & 31)] =
                    w1[(size_t)(hc * 128 + (i >> 5)) * D_ + k0 + (i & 31)];
            }
            __syncthreads();
            if (tid < 64) {
                #pragma unroll
                for (int k = 0; k < 32; k++) {
                    float b0 = Bs[tx * 33 + k], b1 = Bs[(tx + 64) * 33 + k];
                    #pragma unroll
                    for (int mm = 0; mm < 4; mm++) {
                        float a = As[mm * 33 + k];
                        c[mm][0] += a * b0;
                        c[mm][1] += a * b1;
                    }
                }
            } else {
                #pragma unroll
                for (int k = 0; k < 32; k++) {
                    float b0 = Bs[tx * 33 + k], b1 = Bs[(tx + 64) * 33 + k];
                    #pragma unroll
                    for (int mm = 0; mm < 4; mm++) {
                        float a = As[mm * 33 + k];
                        c[mm][0] += a * b0;
                        c[mm][1] += a * b1;
                    }
                }
            }
            __syncthreads();
        }
        // hid tile -> smem (only threads 0..63 write; values replicated in tid>=64 discarded)
        float* hid_s = pool;               // [4][132]
        float* Bs2   = pool + 528;         // [32][257]
        if (tid < 64) {
            int ng = hc * 128 + tx;
            #pragma unroll
            for (int mm = 0; mm < 4; mm++) {
                hid_s[mm * 132 + tx]      = fmaxf(c[mm][0] + b1g[ng], 0.0f);
                hid_s[mm * 132 + tx + 64] = fmaxf(c[mm][1] + b1g[ng + 64], 0.0f);
            }
        }
        __syncthreads();

        // --- mlp2 partial: P[hc][m][n] = hid_tile @ w2[:, hc*128:(hc+1)*128]^T ---
        int txn = tid & 127, tm2 = tid >> 7;
        float d00 = 0, d01 = 0, d10 = 0, d11 = 0;
        for (int k0 = 0; k0 < 128; k0 += 32) {
            #pragma unroll
            for (int r = 0; r < 32; r++) {
                int nrow = (tid >> 5) + r * 8;
                int kl = tid & 31;
                Bs2[kl * 257 + nrow] = w2[(size_t)nrow * HID_ + hc * 128 + k0 + kl];
            }
            __syncthreads();
            #pragma unroll
            for (int k = 0; k < 32; k++) {
                int kk = k0 + k;
                float a0 = hid_s[(2 * tm2) * 132 + kk];
                float a1 = hid_s[(2 * tm2 + 1) * 132 + kk];
                float b0 = Bs2[k * 257 + txn];
                float b1 = Bs2[k * 257 + txn + 128];
                d00 += a0 * b0; d01 += a0 * b1;
                d10 += a1 * b0; d11 += a1 * b1;
            }
            __syncthreads();
        }
        float* P = g_m2p + (size_t)hc * 32768;
        int m = m0 + 2 * tm2;
        P[(size_t)m * D_ + txn]             = d00;
        P[(size_t)m * D_ + txn + 128]       = d01;
        P[(size_t)(m + 1) * D_ + txn]       = d10;
        P[(size_t)(m + 1) * D_ + txn + 128] = d11;
    }
    gsync();

    // ---- P56 fused: reduce partials + bias + residual -> slots (+out / +w-fold) ----
    if (bid < 128) {
        int row = bid, b = row >> 3, k = row & 7, t = tid;
        float v = g_slots[(size_t)row * D_ + t] + b2[t];
        #pragma unroll
        for (int s = 0; s < 8; s++)
            v += g_m2p[(size_t)s * 32768 + (size_t)row * D_ + t];
        g_slots[(size_t)row * D_ + t] = v;
        if (last) {
            out[(size_t)row * D_ + t] = v;
        } else {
            wfold_row(v, b, k, t, tq, tk, ln_sl_g, ln_sl_b, pool, pool + 16);
        }
    }
}

// ------------------- launch -------------------
extern "C" void kernel_launch(void* const* d_in, const int* in_sizes, int n_in,
                              void* d_out, int out_size) {
    const float* emb   = (const float*)d_in[0];
    const float* noise = (const float*)d_in[1];
    const float* mu    = (const float*)d_in[2];
    const float* ls    = (const float*)d_in[3];
    const float* tk    = (const float*)d_in[4];
    const float* tq    = (const float*)d_in[5];
    const float* tv    = (const float*)d_in[6];
    const float* w_ih  = (const float*)d_in[7];
    const float* w_hh  = (const float*)d_in[8];
    const float* b_ih  = (const float*)d_in[9];
    const float* b_hh  = (const float*)d_in[10];
    const float* w1    = (const float*)d_in[11];
    const float* b1    = (const float*)d_in[12];
    const float* w2    = (const float*)d_in[13];
    const float* b2    = (const float*)d_in[14];
    const float* ln_in_g = (const float*)d_in[15];
    const float* ln_in_b = (const float*)d_in[16];
    const float* ln_sl_g = (const float*)d_in[17];
    const float* ln_sl_b = (const float*)d_in[18];
    const float* ln_ff_g = (const float*)d_in[19];
    const float* ln_ff_b = (const float*)d_in[20];

    float* out = (float*)d_out;
    float* vis = out + B_ * K_ * D_;            // slots first, then attn_vis

    const int ATTN_SMEM = (32 * WST + TT_ * EST + 64 * DST + TT_ * 9) * 4;  // ~75.1 KB
    const int MEGA_SMEM = (528 + 32 * 257) * 4 + 256;                        // ~35.3 KB
    cudaFuncSetAttribute(k_attn, cudaFuncAttributeMaxDynamicSharedMemorySize, ATTN_SMEM);
    cudaFuncSetAttribute(k_mega, cudaFuncAttributeMaxDynamicSharedMemorySize, MEGA_SMEM);

    k_init_slots<<<128, 256>>>(mu, ls, noise);
    k_lnemb<<<B_ * N_ / 8, 256>>>(emb, ln_in_g, ln_in_b);
    k_w0<<<128, 256>>>(tq, tk, ln_sl_g, ln_sl_b);

    for (int it = 0; it < 3; it++) {
        k_attn<<<dim3(NT_, 17), 256, ATTN_SMEM>>>(vis, it == 2 ? 1 : 0, w_hh, b_hh);
        k_mega<<<NB2_, 256, MEGA_SMEM>>>(tq, tk, tv, w_ih, b_ih,
                                         w1, b1, w2, b2, ln_sl_g, ln_sl_b,
                                         ln_ff_g, ln_ff_b, it == 2 ? 1 : 0, out);
    }
}

// round 14
// speedup vs baseline: 1.1072x; 1.1072x over previous
#include <cuda_runtime.h>
#include <math.h>

#define B_ 16
#define N_ 2048
#define D_ 256
#define K_ 8
#define H_ 4
#define HID_ 1024
#define LN_EPS 1e-5f
#define SCALEF 0.0625f   // 256^-0.5
#define TT_ 32           // tokens per attn tile
#define NT_ 64           // token tiles (N_/TT_)
#define EST 260          // emb_sh row stride (floats)
#define WST 260          // w_sh row stride
#define DST 36           // dots_sh row stride (conflict-free scatter)
#define NB2_ 256         // mega-kernel blocks

// packed f32x2 FMA helpers
#define FMA2(acc, a, b) \
    asm("fma.rn.f32x2 %0, %1, %2, %0;" : "+l"(acc) : "l"(a), "l"(b))
#define DUP2(dst, f) \
    asm("mov.b64 %0, {%1, %1};" : "=l"(dst) : "f"(f))
#define UNPK2(lo, hi, v) \
    asm("mov.b64 {%0, %1}, %2;" : "=f"(lo), "=f"(hi) : "l"(v))

// ------------------- static device scratch (no allocations) -------------------
static __device__ float g_emb  [B_*N_*D_];
static __device__ float g_slots[B_*K_*D_];
static __device__ float g_w    [B_*K_*H_*D_];     // folded weights [b][kh][e]
static __device__ float g_aggp [B_*NT_*K_*D_];
static __device__ float g_rsp  [B_*NT_*K_];
static __device__ float g_updp [2*B_*K_*D_];
static __device__ float g_gi   [B_*K_*3*D_];
static __device__ float g_gh   [B_*K_*3*D_];
static __device__ float g_pre  [B_*K_*D_];
static __device__ float g_m2p  [8*B_*K_*D_];      // mlp2 split-K partials

// device barrier state
static __device__ unsigned          g_cnt = 0;
static __device__ volatile unsigned g_gen = 0;

__device__ __forceinline__ void gsync() {
    __syncthreads();
    if (threadIdx.x == 0) {
        __threadfence();
        unsigned gen = g_gen;
        if (atomicAdd(&g_cnt, 1) == NB2_ - 1) {
            g_cnt = 0;
            __threadfence();
            g_gen = gen + 1;
        } else {
            while (g_gen == gen) { }
        }
        __threadfence();
    }
    __syncthreads();
}

// ---- shared body: slot value x for row (b,k) -> LN(ln_sl) -> q -> fold w (full row) ----
__device__ __forceinline__ void wfold_row(float x, int b, int k, int t,
                                          const float* __restrict__ tq,
                                          const float* __restrict__ tk,
                                          const float* __restrict__ lg,
                                          const float* __restrict__ lb,
                                          float* red, float* q_sh) {
    float s = x, q = x * x;
    #pragma unroll
    for (int o = 16; o; o >>= 1) {
        s += __shfl_xor_sync(0xffffffffu, s, o);
        q += __shfl_xor_sync(0xffffffffu, q, o);
    }
    if ((t & 31) == 0) { red[t >> 5] = s; red[8 + (t >> 5)] = q; }
    __syncthreads();
    float S = 0.0f, Q = 0.0f;
    #pragma unroll
    for (int i = 0; i < 8; i++) { S += red[i]; Q += red[8 + i]; }
    float m  = S * (1.0f / D_);
    float rs = rsqrtf(Q * (1.0f / D_) - m * m + LN_EPS);
    float sv = (x - m) * rs * lg[t] + lb[t];
    q_sh[t] = sv * tq[(size_t)k * 65536 + t * 257];
    __syncthreads();
    const float* tr = tk + (size_t)k * 65536 + (size_t)t * D_;
    #pragma unroll
    for (int h = 0; h < H_; h++) {
        const float4* r4 = (const float4*)(tr + h * 64);
        const float4* q4 = (const float4*)(q_sh + h * 64);
        float a = 0.0f;
        #pragma unroll
        for (int j = 0; j < 16; j++) {
            float4 rv = r4[j], qv = q4[j];
            a += rv.x*qv.x + rv.y*qv.y + rv.z*qv.z + rv.w*qv.w;
        }
        g_w[((size_t)(b * 32 + k * 4 + h)) * D_ + t] = SCALEF * a;
    }
}

// ------------------- fused setup: slot-init + w-fold (blocks<128) | emb LN (blocks>=128) ----
__global__ __launch_bounds__(256) void k_setup(
    const float* __restrict__ xin, const float* __restrict__ nz,
    const float* __restrict__ mu, const float* __restrict__ ls,
    const float* __restrict__ tq, const float* __restrict__ tk,
    const float* __restrict__ ln_in_g, const float* __restrict__ ln_in_b,
    const float* __restrict__ ln_sl_g, const float* __restrict__ ln_sl_b) {
    __shared__ float red[16];
    __shared__ float q_sh[D_];
    int bid = blockIdx.x, tid = threadIdx.x;

    if (bid < 128) {
        // slots = mu + exp(logsigma)*noise, then immediate w-fold (row is block-local)
        int i = bid * 256 + tid;
        int kd = i & (K_*D_ - 1);
        float x = mu[kd] + __expf(ls[kd]) * nz[i];
        g_slots[i] = x;
        wfold_row(x, bid >> 3, bid & 7, tid, tq, tk, ln_sl_g, ln_sl_b, red, q_sh);
        return;
    }

    // embeddings LayerNorm: 512 blocks x 8 groups, one warp per 256-wide row
    int wid = tid >> 5, lane = tid & 31;
    for (int grp = bid - 128; grp < 4096; grp += 512) {
        size_t row = (size_t)grp * 8 + wid;
        const float* xr = xin + row * D_;
        float4 v0 = ((const float4*)xr)[lane];
        float4 v1 = ((const float4*)xr)[32 + lane];
        float s = v0.x+v0.y+v0.z+v0.w + v1.x+v1.y+v1.z+v1.w;
        float q = v0.x*v0.x+v0.y*v0.y+v0.z*v0.z+v0.w*v0.w
                + v1.x*v1.x+v1.y*v1.y+v1.z*v1.z+v1.w*v1.w;
        #pragma unroll
        for (int o = 16; o; o >>= 1) {
            s += __shfl_xor_sync(0xffffffffu, s, o);
            q += __shfl_xor_sync(0xffffffffu, q, o);
        }
        float m  = s * (1.0f / D_);
        float rs = rsqrtf(q * (1.0f / D_) - m * m + LN_EPS);
        float4 g0 = ((const float4*)ln_in_g)[lane],      b0 = ((const float4*)ln_in_b)[lane];
        float4 g1 = ((const float4*)ln_in_g)[32 + lane], b1 = ((const float4*)ln_in_b)[32 + lane];
        float4 o0, o1;
        o0.x = (v0.x-m)*rs*g0.x + b0.x;  o0.y = (v0.y-m)*rs*g0.y + b0.y;
        o0.z = (v0.z-m)*rs*g0.z + b0.z;  o0.w = (v0.w-m)*rs*g0.w + b0.w;
        o1.x = (v1.x-m)*rs*g1.x + b1.x;  o1.y = (v1.y-m)*rs*g1.y + b1.y;
        o1.z = (v1.z-m)*rs*g1.z + b1.z;  o1.w = (v1.w-m)*rs*g1.w + b1.w;
        ((float4*)(g_emb + row * D_))[lane]      = o0;
        ((float4*)(g_emb + row * D_))[32 + lane] = o1;
    }
}

// ------------------- fused attention v6 (identical to R12 best) -------------------
__global__ __launch_bounds__(256, 3) void k_attn(float* __restrict__ vis, int wvis) {
    extern __shared__ __align__(16) float sm[];
    float* w_sh    = sm;                    // [kh][e]   32*WST (reused as reduction buffer)
    float* emb_sh  = w_sh + 32 * WST;       // [t][e]    32*EST
    float* dots_sh = emb_sh + TT_ * EST;    // [eh][t][kh] 64*DST
    float* att_sh  = dots_sh + 64 * DST;    // [t][k]    32*9

    int tid = threadIdx.x, lane = tid & 31, wid = tid >> 5;
    int b = blockIdx.y;
    int tile = blockIdx.x;
    int nb = tile * TT_;

    const float4* wsrc = (const float4*)(g_w + (size_t)b * 8192);
    #pragma unroll
    for (int r = 0; r < 8; r++) {
        int j = tid + r * 256;
        *(float4*)(w_sh + (j >> 6) * WST + (j & 63) * 4) = wsrc[j];
    }
    const float4* esrc = (const float4*)(g_emb + ((size_t)(b * N_ + nb)) * D_);
    #pragma unroll
    for (int r = 0; r < 8; r++) {
        int j = tid + r * 256;
        *(float4*)(emb_sh + (j >> 6) * EST + (j & 63) * 4) = esrc[j];
    }
    __syncthreads();

    {
        int unit = wid >> 1, eh = wid & 1;
        int tbase  = (unit >> 1) * 16;
        int khbase = (unit & 1) * 16;
        int lt = lane >> 2, lk = lane & 3;
        int t0  = tbase + lt;
        int kh0 = khbase + lk;
        int e0 = eh * 128;
        const float* eb0 = emb_sh + t0 * EST + e0;
        const float* wb0 = w_sh + kh0 * WST + e0;
        unsigned long long acc2[2][4];
        #pragma unroll
        for (int i = 0; i < 2; i++)
            #pragma unroll
            for (int j = 0; j < 4; j++) acc2[i][j] = 0ull;

        #pragma unroll 4
        for (int e = 0; e < 128; e += 4) {
            ulonglong2 ev0 = *(const ulonglong2*)(eb0 + e);
            ulonglong2 ev1 = *(const ulonglong2*)(eb0 + 8 * EST + e);
            #pragma unroll
            for (int j = 0; j < 4; j++) {
                ulonglong2 wv = *(const ulonglong2*)(wb0 + (4 * j) * WST + e);
                FMA2(acc2[0][j], ev0.x, wv.x);
                FMA2(acc2[0][j], ev0.y, wv.y);
                FMA2(acc2[1][j], ev1.x, wv.x);
                FMA2(acc2[1][j], ev1.y, wv.y);
            }
        }
        #pragma unroll
        for (int i = 0; i < 2; i++)
            #pragma unroll
            for (int j = 0; j < 4; j++) {
                float lo, hi; UNPK2(lo, hi, acc2[i][j]);
                dots_sh[(eh * 32 + t0 + 8 * i) * DST + kh0 + 4 * j] = lo + hi;
            }
    }
    __syncthreads();

    if (tid < 128) {
        int t = tid >> 2, h = tid & 3;
        float d[8], mx = -1e30f;
        #pragma unroll
        for (int k = 0; k < 8; k++) {
            d[k] = dots_sh[t * DST + k*4 + h] + dots_sh[(32 + t) * DST + k*4 + h];
            mx = fmaxf(mx, d[k]);
        }
        float smx = 0.0f;
        #pragma unroll
        for (int k = 0; k < 8; k++) { d[k] = __expf(d[k] - mx); smx += d[k]; }
        float inv = 1.0f / smx;
        #pragma unroll
        for (int k = 0; k < 8; k++) {
            float v = d[k] * inv;
            v += __shfl_xor_sync(0xffffffffu, v, 1);
            v += __shfl_xor_sync(0xffffffffu, v, 2);
            if (h == 0) att_sh[t * 9 + k] = v * 0.25f;
        }
    }
    __syncthreads();

    {
        float rs = att_sh[lane * 9 + wid];
        #pragma unroll
        for (int o = 16; o; o >>= 1) rs += __shfl_xor_sync(0xffffffffu, rs, o);
        if (lane == 0) g_rsp[((size_t)b * NT_ + tile) * K_ + wid] = rs;
        if (wvis)
            vis[((size_t)b * K_ + wid) * N_ + nb + lane] = att_sh[lane * 9 + wid];
    }

    {
        int ts = tid >> 6, eg = tid & 63;
        unsigned long long acc[8][2];
        #pragma unroll
        for (int k = 0; k < 8; k++) { acc[k][0] = 0ull; acc[k][1] = 0ull; }
        const float* ebase = emb_sh + eg * 4;
        #pragma unroll
        for (int tt = 0; tt < 8; tt++) {
            int t = ts * 8 + tt;
            ulonglong2 ev = *(const ulonglong2*)(ebase + t * EST);
            #pragma unroll
            for (int k = 0; k < 8; k++) {
                float a = att_sh[t * 9 + k];
                unsigned long long aa; DUP2(aa, a);
                FMA2(acc[k][0], ev.x, aa);
                FMA2(acc[k][1], ev.y, aa);
            }
        }
        float* red = w_sh;
        #pragma unroll
        for (int k = 0; k < 8; k++) {
            float f0, f1, f2, f3;
            UNPK2(f0, f1, acc[k][0]);
            UNPK2(f2, f3, acc[k][1]);
            *(float4*)(red + (ts * 8 + k) * 256 + eg * 4) = make_float4(f0, f1, f2, f3);
        }
    }
    __syncthreads();
    {
        const float* red = w_sh;
        #pragma unroll
        for (int r = 0; r < 8; r++) {
            int idx = tid + r * 256;
            int k = idx >> 8, e = idx & 255;
            float s = red[k * 256 + e] + red[(8 + k) * 256 + e]
                    + red[(16 + k) * 256 + e] + red[(24 + k) * 256 + e];
            g_aggp[(((size_t)(b * NT_ + tile)) * K_ + k) * D_ + e] = s;
        }
    }
}

// ------------------- mega-kernel v2 (identical to R12 best) -------------------
__global__ __launch_bounds__(256, 2) void k_mega(
    const float* __restrict__ tq, const float* __restrict__ tk, const float* __restrict__ tv,
    const float* __restrict__ wih, const float* __restrict__ whh,
    const float* __restrict__ bih, const float* __restrict__ bhh,
    const float* __restrict__ w1, const float* __restrict__ b1g,
    const float* __restrict__ w2, const float* __restrict__ b2,
    const float* __restrict__ ln_sl_g, const float* __restrict__ ln_sl_b,
    const float* __restrict__ ln_ff_g, const float* __restrict__ ln_ff_b,
    int last, float* __restrict__ out)
{
    extern __shared__ __align__(16) float pool[];
    int bid = blockIdx.x, tid = threadIdx.x;

    // ---- P0: upd partials. block = (row, e-half). ----
    {
        int row = bid >> 1, half = bid & 1, b = row >> 3, k = row & 7;
        int e0 = half * 128;
        float acc = 0.0f;
        int e = e0 + (tid & 127);
        int tb = (tid < 128) ? 0 : 32;
        const float* base = g_aggp + ((size_t)(b * NT_) * K_ + k) * D_ + e;
        #pragma unroll 8
        for (int tile = 0; tile < 32; tile++)
            acc += base[(size_t)(tb + tile) * (K_ * D_)];
        pool[tid] = acc;
        if (tid == 0) {
            float r = 0.0f;
            #pragma unroll
            for (int tile = 0; tile < NT_; tile++)
                r += g_rsp[((size_t)b * NT_ + tile) * K_ + k];
            pool[2048] = 1.0f / r;
        }
        __syncthreads();
        const float* tvk = tv + (size_t)k * 65536 + (size_t)e0 * D_ + tid;
        float mv = 0.0f;
        #pragma unroll 8
        for (int e2 = 0; e2 < 128; e2++)
            mv += (pool[e2] + pool[128 + e2]) * __ldg(tvk + (size_t)e2 * D_);
        g_updp[(size_t)half * 32768 + (size_t)row * D_ + tid] = mv * pool[2048];
    }
    gsync();

    // ---- P1: GRU pre-activations, 32x32 tiles (192 blocks) ----
    if (bid < 192) {
        int gsel = (bid >= 96) ? 1 : 0;
        int t2 = gsel ? bid - 96 : bid;
        int m0 = (t2 / 24) * 32, n0 = (t2 % 24) * 32;
        float* As = pool; float* Bs = pool + 32 * 33;
        const float* Bm  = gsel ? whh : wih;
        const float* bia = gsel ? bhh : bih;
        float* C = gsel ? g_gh : g_gi;
        int tx = tid & 15, ty = tid >> 4;
        float c00 = 0, c01 = 0, c10 = 0, c11 = 0;
        for (int k0 = 0; k0 < D_; k0 += 32) {
            #pragma unroll
            for (int r = 0; r < 4; r++) {
                int i = tid + r * 256;
                int m = m0 + (i >> 5), d = k0 + (i & 31);
                float av;
                if (gsel) av = g_slots[(size_t)m * D_ + d];
                else av = g_updp[(size_t)m * D_ + d] + g_updp[32768 + (size_t)m * D_ + d];
                As[(i >> 5) * 33 + (i & 31)] = av;
                Bs[(i >> 5) * 33 + (i & 31)] = Bm[(size_t)(n0 + (i >> 5)) * D_ + d];
            }
            __syncthreads();
            #pragma unroll
            for (int k = 0; k < 32; k++) {
                float a0 = As[(ty*2)*33 + k], a1 = As[(ty*2+1)*33 + k];
                float b0 = Bs[(tx*2)*33 + k], b1 = Bs[(tx*2+1)*33 + k];
                c00 += a0*b0; c01 += a0*b1; c10 += a1*b0; c11 += a1*b1;
            }
            __syncthreads();
        }
        int m = m0 + ty*2, n = n0 + tx*2;
        C[(size_t)m * 768 + n]       = c00 + bia[n];
        C[(size_t)m * 768 + n+1]     = c01 + bia[n+1];
        C[(size_t)(m+1) * 768 + n]   = c10 + bia[n];
        C[(size_t)(m+1) * 768 + n+1] = c11 + bia[n+1];
    }
    gsync();

    // ---- P2: GRU gates + pre-MLP LayerNorm(ff) (128 blocks) ----
    if (bid < 128) {
        float* red = pool;
        int row = bid, t = tid;
        const float* gi = g_gi + (size_t)row * 768;
        const float* gh = g_gh + (size_t)row * 768;
        float ir = gi[t], iz = gi[256 + t], in_ = gi[512 + t];
        float hr = gh[t], hz = gh[256 + t], hn  = gh[512 + t];
        float r = 1.0f / (1.0f + __expf(-(ir + hr)));
        float z = 1.0f / (1.0f + __expf(-(iz + hz)));
        float n = tanhf(in_ + r * hn);
        float h = g_slots[(size_t)row * D_ + t];
        float s = (1.0f - z) * n + z * h;
        g_slots[(size_t)row * D_ + t] = s;
        float a = s, q = s * s;
        #pragma unroll
        for (int o = 16; o; o >>= 1) {
            a += __shfl_xor_sync(0xffffffffu, a, o);
            q += __shfl_xor_sync(0xffffffffu, q, o);
        }
        if ((t & 31) == 0) { red[t >> 5] = a; red[8 + (t >> 5)] = q; }
        __syncthreads();
        float S = 0.0f, Q = 0.0f;
        #pragma unroll
        for (int i = 0; i < 8; i++) { S += red[i]; Q += red[8 + i]; }
        float m  = S * (1.0f / D_);
        float rs = rsqrtf(Q * (1.0f / D_) - m * m + LN_EPS);
        g_pre[(size_t)row * D_ + t] = (s - m) * rs * ln_ff_g[t] + ln_ff_b[t];
    }
    gsync();

    // ---- P34 fused: mlp1 tile (4m x 128n, hid in smem) -> mlp2 split-K partial ----
    {
        int mt = bid >> 3, hc = bid & 7;
        int m0 = mt * 4;
        float* As = pool;            // [4][33]
        float* Bs = pool + 132;      // [128][33]
        int tx = tid & 63, tm = tid >> 6;       // thread: m = m0+tm ; n = tx, tx+64
        float c0 = 0.0f, c1 = 0.0f;
        for (int k0 = 0; k0 < D_; k0 += 32) {
            if (tid < 128)
                As[(tid >> 5) * 33 + (tid & 31)] =
                    g_pre[(size_t)(m0 + (tid >> 5)) * D_ + k0 + (tid & 31)];
            #pragma unroll
            for (int r = 0; r < 16; r++) {
                int i = tid + r * 256;
                Bs[(i >> 5) * 33 + (i & 31)] =
                    w1[(size_t)(hc * 128 + (i >> 5)) * D_ + k0 + (i & 31)];
            }
            __syncthreads();
            #pragma unroll
            for (int k = 0; k < 32; k++) {
                float a = As[tm * 33 + k];
                c0 += a * Bs[tx * 33 + k];
                c1 += a * Bs[(tx + 64) * 33 + k];
            }
            __syncthreads();
        }
        float* hid_s = pool;               // [4][132]
        float* Bs2   = pool + 528;         // [32][257]
        int ng = hc * 128 + tx;
        hid_s[tm * 132 + tx]      = fmaxf(c0 + b1g[ng], 0.0f);
        hid_s[tm * 132 + tx + 64] = fmaxf(c1 + b1g[ng + 64], 0.0f);
        __syncthreads();

        int txn = tid & 127, tm2 = tid >> 7;
        float d00 = 0, d01 = 0, d10 = 0, d11 = 0;
        for (int k0 = 0; k0 < 128; k0 += 32) {
            #pragma unroll
            for (int r = 0; r < 32; r++) {
                int nrow = (tid >> 5) + r * 8;
                int kl = tid & 31;
                Bs2[kl * 257 + nrow] = w2[(size_t)nrow * HID_ + hc * 128 + k0 + kl];
            }
            __syncthreads();
            #pragma unroll
            for (int k = 0; k < 32; k++) {
                int kk = k0 + k;
                float a0 = hid_s[(2 * tm2) * 132 + kk];
                float a1 = hid_s[(2 * tm2 + 1) * 132 + kk];
                float b0 = Bs2[k * 257 + txn];
                float b1 = Bs2[k * 257 + txn + 128];
                d00 += a0 * b0; d01 += a0 * b1;
                d10 += a1 * b0; d11 += a1 * b1;
            }
            __syncthreads();
        }
        float* P = g_m2p + (size_t)hc * 32768;
        int m = m0 + 2 * tm2;
        P[(size_t)m * D_ + txn]             = d00;
        P[(size_t)m * D_ + txn + 128]       = d01;
        P[(size_t)(m + 1) * D_ + txn]       = d10;
        P[(size_t)(m + 1) * D_ + txn + 128] = d11;
    }
    gsync();

    // ---- P56 fused: reduce partials + bias + residual -> slots (+out / +w-fold) ----
    if (bid < 128) {
        int row = bid, b = row >> 3, k = row & 7, t = tid;
        float v = g_slots[(size_t)row * D_ + t] + b2[t];
        #pragma unroll
        for (int s = 0; s < 8; s++)
            v += g_m2p[(size_t)s * 32768 + (size_t)row * D_ + t];
        g_slots[(size_t)row * D_ + t] = v;
        if (last) {
            out[(size_t)row * D_ + t] = v;
        } else {
            wfold_row(v, b, k, t, tq, tk, ln_sl_g, ln_sl_b, pool, pool + 16);
        }
    }
}

// ------------------- launch -------------------
extern "C" void kernel_launch(void* const* d_in, const int* in_sizes, int n_in,
                              void* d_out, int out_size) {
    const float* emb   = (const float*)d_in[0];
    const float* noise = (const float*)d_in[1];
    const float* mu    = (const float*)d_in[2];
    const float* ls    = (const float*)d_in[3];
    const float* tk    = (const float*)d_in[4];
    const float* tq    = (const float*)d_in[5];
    const float* tv    = (const float*)d_in[6];
    const float* w_ih  = (const float*)d_in[7];
    const float* w_hh  = (const float*)d_in[8];
    const float* b_ih  = (const float*)d_in[9];
    const float* b_hh  = (const float*)d_in[10];
    const float* w1    = (const float*)d_in[11];
    const float* b1    = (const float*)d_in[12];
    const float* w2    = (const float*)d_in[13];
    const float* b2    = (const float*)d_in[14];
    const float* ln_in_g = (const float*)d_in[15];
    const float* ln_in_b = (const float*)d_in[16];
    const float* ln_sl_g = (const float*)d_in[17];
    const float* ln_sl_b = (const float*)d_in[18];
    const float* ln_ff_g = (const float*)d_in[19];
    const float* ln_ff_b = (const float*)d_in[20];

    float* out = (float*)d_out;
    float* vis = out + B_ * K_ * D_;            // slots first, then attn_vis

    const int ATTN_SMEM = (32 * WST + TT_ * EST + 64 * DST + TT_ * 9) * 4;  // ~75.1 KB
    const int MEGA_SMEM = (528 + 32 * 257) * 4 + 256;                        // ~35.3 KB
    cudaFuncSetAttribute(k_attn, cudaFuncAttributeMaxDynamicSharedMemorySize, ATTN_SMEM);
    cudaFuncSetAttribute(k_mega, cudaFuncAttributeMaxDynamicSharedMemorySize, MEGA_SMEM);

    k_setup<<<640, 256>>>(emb, noise, mu, ls, tq, tk,
                          ln_in_g, ln_in_b, ln_sl_g, ln_sl_b);

    for (int it = 0; it < 3; it++) {
        k_attn<<<dim3(NT_, 16), 256, ATTN_SMEM>>>(vis, it == 2 ? 1 : 0);
        k_mega<<<NB2_, 256, MEGA_SMEM>>>(tq, tk, tv, w_ih, w_hh, b_ih, b_hh,
                                         w1, b1, w2, b2, ln_sl_g, ln_sl_b,
                                         ln_ff_g, ln_ff_b, it == 2 ? 1 : 0, out);
    }
}